// round 15
// baseline (speedup 1.0000x reference)
#include <cuda_runtime.h>
#include <cuda_bf16.h>
#include <cuda_fp16.h>
#include <cstdint>

#define N_NODES 40000
#define DFEAT   128
#define N_EDGES 640000
#define SCAN_BLOCKS 40            // 40*1024 = 40960 >= 40000

// Scratch (static device globals — no allocation). Zero-initialized at load;
// g_deg / g_cnt are re-zeroed by k_fill each call so every graph replay sees
// identical state.
__device__ int   g_deg[N_NODES];
__device__ int   g_off[N_NODES + 1];        // CSR row offsets
__device__ int   g_rank[N_EDGES];           // per-edge rank within dst node
__device__ int   g_csrc[N_EDGES];           // CSR-ordered source indices
__device__ int   g_bsum[SCAN_BLOCKS];       // scan block totals
__device__ int   g_cnt;                     // scan grid-barrier counter
__device__ __half        g_nh[N_NODES * DFEAT];   // ndata fp16 (neighbor cache)
__device__ __nv_bfloat16 g_hh[N_NODES * DFEAT];   // h hi (bf16)
__device__ __nv_bfloat16 g_hl[N_NODES * DFEAT];   // h lo (bf16)
__device__ __nv_bfloat16 g_wh[DFEAT * DFEAT];     // W hi
__device__ __nv_bfloat16 g_wl[DFEAT * DFEAT];     // W lo

// ===========================================================================
// PTX helpers — baseline PTX only (sm_80+ mma.sync / sm_75+ ldmatrix).
// ===========================================================================
__device__ __forceinline__ uint32_t smem_u32(const void* p) {
    uint32_t a;
    asm("{ .reg .u64 t; cvta.to.shared.u64 t, %1; cvt.u32.u64 %0, t; }"
        : "=r"(a) : "l"(p));
    return a;
}

#define LDSM_X4(r0, r1, r2, r3, addr) \
    asm volatile("ldmatrix.sync.aligned.m8n8.x4.shared.b16 {%0,%1,%2,%3}, [%4];" \
                 : "=r"(r0), "=r"(r1), "=r"(r2), "=r"(r3) : "r"(addr))

#define MMA_BF16(c, a, b0, b1) \
    asm volatile("mma.sync.aligned.m16n8k16.row.col.f32.bf16.bf16.f32 " \
                 "{%0,%1,%2,%3}, {%4,%5,%6,%7}, {%8,%9}, {%0,%1,%2,%3};" \
                 : "+f"((c)[0]), "+f"((c)[1]), "+f"((c)[2]), "+f"((c)[3]) \
                 : "r"((a)[0]), "r"((a)[1]), "r"((a)[2]), "r"((a)[3]), \
                   "r"(b0), "r"(b1))

__device__ __forceinline__ uint32_t pack_hi2(float x, float y,
                                             float& rx, float& ry) {
    __nv_bfloat16 hx = __float2bfloat16(x);
    __nv_bfloat16 hy = __float2bfloat16(y);
    rx = x - __bfloat162float(hx);
    ry = y - __bfloat162float(hy);
    return ((uint32_t)__bfloat16_as_ushort(hy) << 16) | __bfloat16_as_ushort(hx);
}
__device__ __forceinline__ uint32_t pack_lo2(float rx, float ry) {
    __nv_bfloat16 lx = __float2bfloat16(rx);
    __nv_bfloat16 ly = __float2bfloat16(ry);
    return ((uint32_t)__bfloat16_as_ushort(ly) << 16) | __bfloat16_as_ushort(lx);
}

// ===========================================================================
// k_head: FUSED  deg histogram + rank capture  ∥  ndata fp32->fp16 convert
//         ∥  W bf16 hi/lo split.
// ===========================================================================
__global__ void k_head(const float* __restrict__ ndata,
                       const float* __restrict__ W,
                       const int* __restrict__ dst) {
    int i = blockIdx.x * blockDim.x + threadIdx.x;

    if (i < N_EDGES / 4) {                      // deg + rank (groups of 4)
        int4 d = __ldg(reinterpret_cast<const int4*>(dst) + i);
        int4 r;
        r.x = atomicAdd(&g_deg[d.x], 1);
        r.y = atomicAdd(&g_deg[d.y], 1);
        r.z = atomicAdd(&g_deg[d.z], 1);
        r.w = atomicAdd(&g_deg[d.w], 1);
        reinterpret_cast<int4*>(g_rank)[i] = r;
    }
    if (i < DFEAT * DFEAT / 4) {                // W split
        float4 v = __ldg(reinterpret_cast<const float4*>(W) + i);
        float r0, r1, r2, r3;
        uint32_t hiA = pack_hi2(v.x, v.y, r0, r1);
        uint32_t hiB = pack_hi2(v.z, v.w, r2, r3);
        uint32_t loA = pack_lo2(r0, r1);
        uint32_t loB = pack_lo2(r2, r3);
        reinterpret_cast<uint2*>(g_wh)[i] = make_uint2(hiA, hiB);
        reinterpret_cast<uint2*>(g_wl)[i] = make_uint2(loA, loB);
    }
    if (i < N_NODES * DFEAT / 4) {              // fp16 neighbor cache
        float4 v = __ldg(reinterpret_cast<const float4*>(ndata) + i);
        __half2 a = __floats2half2_rn(v.x, v.y);
        __half2 b = __floats2half2_rn(v.z, v.w);
        uint2 o;
        o.x = *reinterpret_cast<uint32_t*>(&a);
        o.y = *reinterpret_cast<uint32_t*>(&b);
        reinterpret_cast<uint2*>(g_nh)[i] = o;
    }
}

// ===========================================================================
// k_scan: single-kernel exclusive scan over 40000 degrees.
// 40 co-resident blocks + software grid barrier on g_cnt.
// ===========================================================================
__global__ __launch_bounds__(1024) void k_scan() {
    __shared__ int sh[1024];
    __shared__ int s_bpre;
    int b = blockIdx.x, tid = threadIdx.x;
    int i = b * 1024 + tid;
    int v = (i < N_NODES) ? g_deg[i] : 0;
    int val = v;
    sh[tid] = val;
    __syncthreads();
    for (int s = 1; s < 1024; s <<= 1) {
        int o = (tid >= s) ? sh[tid - s] : 0;
        __syncthreads();
        val += o;
        sh[tid] = val;
        __syncthreads();
    }
    if (tid == 1023) {
        g_bsum[b] = val;
        __threadfence();
        atomicAdd(&g_cnt, 1);
    }
    if (tid == 0) {
        while (atomicAdd(&g_cnt, 0) < SCAN_BLOCKS) { }
    }
    __syncthreads();
    if (tid < SCAN_BLOCKS) sh[tid] = atomicAdd(&g_bsum[tid], 0);
    __syncthreads();
    if (tid == 0) {
        int p = 0;
        for (int j = 0; j < b; j++) p += sh[j];
        s_bpre = p;
        if (b == SCAN_BLOCKS - 1) g_off[N_NODES] = p + sh[SCAN_BLOCKS - 1];
    }
    __syncthreads();
    if (i < N_NODES) g_off[i] = (val - v) + s_bpre;
}

// ===========================================================================
// k_fill: atomic-free scatter — position = g_off[dst] + rank.
// x8 edge batching; also re-zeros g_deg / g_cnt for the next replay.
// ===========================================================================
__global__ void k_fill(const int* __restrict__ src,
                       const int* __restrict__ dst) {
    int t = blockIdx.x * blockDim.x + threadIdx.x;   // over groups of 8
    if (t < N_EDGES / 8) {
        const int4* d4 = reinterpret_cast<const int4*>(dst) + t * 2;
        const int4* s4 = reinterpret_cast<const int4*>(src) + t * 2;
        const int4* r4 = reinterpret_cast<const int4*>(g_rank) + t * 2;
        int4 d0 = __ldg(d4);
        int4 d1 = __ldg(d4 + 1);
        int4 s0 = __ldg(s4);
        int4 s1 = __ldg(s4 + 1);
        int4 r0 = __ldg(r4);
        int4 r1 = __ldg(r4 + 1);
        int o0 = __ldg(&g_off[d0.x]);
        int o1 = __ldg(&g_off[d0.y]);
        int o2 = __ldg(&g_off[d0.z]);
        int o3 = __ldg(&g_off[d0.w]);
        int o4 = __ldg(&g_off[d1.x]);
        int o5 = __ldg(&g_off[d1.y]);
        int o6 = __ldg(&g_off[d1.z]);
        int o7 = __ldg(&g_off[d1.w]);
        g_csrc[o0 + r0.x] = s0.x;
        g_csrc[o1 + r0.y] = s0.y;
        g_csrc[o2 + r0.z] = s0.z;
        g_csrc[o3 + r0.w] = s0.w;
        g_csrc[o4 + r1.x] = s1.x;
        g_csrc[o5 + r1.y] = s1.y;
        g_csrc[o6 + r1.z] = s1.z;
        g_csrc[o7 + r1.w] = s1.w;
    }
    if (t < N_NODES) g_deg[t] = 0;
    if (t == 0) g_cnt = 0;
}

// ===========================================================================
// k_gather: one warp per node. Pairwise HADD2 (fp16) then fp32 accumulate;
// int4 index loads (segment aligned to 4). Emits bf16 hi/lo of h.
// ===========================================================================
__global__ __launch_bounds__(256) void k_gather(const float* __restrict__ ndata) {
    int gt   = blockIdx.x * blockDim.x + threadIdx.x;
    int v    = gt >> 5;
    int lane = gt & 31;
    if (v >= N_NODES) return;

    int off0 = g_off[v];
    int off1 = g_off[v + 1];
    int d    = off1 - off0;
    float inv = 1.0f / (float)(d > 0 ? d : 1);

    const uint2* nh = reinterpret_cast<const uint2*>(g_nh);   // row stride 32

    float4 acc = make_float4(0.f, 0.f, 0.f, 0.f);

    int i = off0;
    // scalar prologue: align i to multiple of 4 (exact fp32 adds)
    int lim = (off0 + 3) & ~3;
    if (lim > off1) lim = off1;
    for (; i < lim; i++) {
        int s = __ldg(g_csrc + i);
        uint2 p = __ldg(nh + (size_t)s * 32 + lane);
        float2 a = __half22float2(*reinterpret_cast<__half2*>(&p.x));
        float2 b = __half22float2(*reinterpret_cast<__half2*>(&p.y));
        acc.x += a.x; acc.y += a.y; acc.z += b.x; acc.w += b.y;
    }
    // main loop: 4 edges per iter, one int4 index load, pairwise HADD2
    for (; i + 4 <= off1; i += 4) {
        int4 s = __ldg(reinterpret_cast<const int4*>(g_csrc) + (i >> 2));
        uint2 p0 = __ldg(nh + (size_t)s.x * 32 + lane);
        uint2 p1 = __ldg(nh + (size_t)s.y * 32 + lane);
        uint2 p2 = __ldg(nh + (size_t)s.z * 32 + lane);
        uint2 p3 = __ldg(nh + (size_t)s.w * 32 + lane);
        __half2 a01 = __hadd2(*reinterpret_cast<__half2*>(&p0.x),
                              *reinterpret_cast<__half2*>(&p1.x));
        __half2 b01 = __hadd2(*reinterpret_cast<__half2*>(&p0.y),
                              *reinterpret_cast<__half2*>(&p1.y));
        __half2 a23 = __hadd2(*reinterpret_cast<__half2*>(&p2.x),
                              *reinterpret_cast<__half2*>(&p3.x));
        __half2 b23 = __hadd2(*reinterpret_cast<__half2*>(&p2.y),
                              *reinterpret_cast<__half2*>(&p3.y));
        float2 fa0 = __half22float2(a01);
        float2 fb0 = __half22float2(b01);
        float2 fa1 = __half22float2(a23);
        float2 fb1 = __half22float2(b23);
        acc.x += fa0.x + fa1.x;
        acc.y += fa0.y + fa1.y;
        acc.z += fb0.x + fb1.x;
        acc.w += fb0.y + fb1.y;
    }
    // scalar epilogue
    for (; i < off1; i++) {
        int s = __ldg(g_csrc + i);
        uint2 p = __ldg(nh + (size_t)s * 32 + lane);
        float2 a = __half22float2(*reinterpret_cast<__half2*>(&p.x));
        float2 b = __half22float2(*reinterpret_cast<__half2*>(&p.y));
        acc.x += a.x; acc.y += a.y; acc.z += b.x; acc.w += b.y;
    }

    float4 self = __ldg(reinterpret_cast<const float4*>(ndata + (size_t)v * DFEAT) + lane);
    float4 h;
    h.x = self.x + acc.x * inv;
    h.y = self.y + acc.y * inv;
    h.z = self.z + acc.z * inv;
    h.w = self.w + acc.w * inv;

    float r0, r1, r2, r3;
    uint32_t hiA = pack_hi2(h.x, h.y, r0, r1);
    uint32_t hiB = pack_hi2(h.z, h.w, r2, r3);
    uint32_t loA = pack_lo2(r0, r1);
    uint32_t loB = pack_lo2(r2, r3);

    size_t o = (size_t)v * DFEAT / 4 + lane;   // uint2 index
    reinterpret_cast<uint2*>(g_hh)[o] = make_uint2(hiA, hiB);
    reinterpret_cast<uint2*>(g_hl)[o] = make_uint2(loA, loB);
}

// ===========================================================================
// k_gemm_mma: out[40000,128] = h @ W^T + b  (bf16 split, 3 terms, fp32 accum)
// BM=160, BN=128; grid 250; 320 threads = 10 warps (5 M x 2 N).
// ===========================================================================
#define TSTRIDE   72
#define ROWB      (TSTRIDE * 2)                 // 144 B per row
#define A_HI_OFF  0
#define A_LO_OFF  (160 * ROWB)                  // 23040
#define B_HI_OFF  (2 * 160 * ROWB)              // 46080
#define B_LO_OFF  (B_HI_OFF + 128 * ROWB)       // 64512
#define SMEM_GEMM (B_LO_OFF + 128 * ROWB)       // 82944

__global__ __launch_bounds__(320, 2) void k_gemm_mma(const float* __restrict__ bias,
                                                     float* __restrict__ out) {
    extern __shared__ char smem[];
    uint32_t sb = smem_u32(smem);
    int tid  = threadIdx.x;
    int wid  = tid >> 5;
    int lane = tid & 31;
    int wm = wid % 5;
    int wn = wid / 5;
    int blockRow = blockIdx.x * 160;

    float acc[2][8][4];
#pragma unroll
    for (int mt = 0; mt < 2; mt++)
#pragma unroll
        for (int nt = 0; nt < 8; nt++)
#pragma unroll
            for (int c = 0; c < 4; c++) acc[mt][nt][c] = 0.0f;

    for (int r = 0; r < 2; r++) {
        int k0 = r * 64;

        for (int idx = tid; idx < 4608; idx += 320) {
            uint4 v;
            uint32_t soff;
            if (idx < 2560) {
                int isLo = idx >= 1280;
                int q    = isLo ? idx - 1280 : idx;
                int row  = q >> 3;
                int c8   = q & 7;
                const __nv_bfloat16* srcb = isLo ? g_hl : g_hh;
                v = __ldg(reinterpret_cast<const uint4*>(
                        srcb + (size_t)(blockRow + row) * DFEAT + k0) + c8);
                soff = (isLo ? A_LO_OFF : A_HI_OFF) + (uint32_t)row * ROWB + c8 * 16;
            } else {
                int q2   = idx - 2560;
                int isLo = q2 >= 1024;
                int q    = isLo ? q2 - 1024 : q2;
                int row  = q >> 3;
                int c8   = q & 7;
                const __nv_bfloat16* srcb = isLo ? g_wl : g_wh;
                v = __ldg(reinterpret_cast<const uint4*>(
                        srcb + (size_t)row * DFEAT + k0) + c8);
                soff = (isLo ? B_LO_OFF : B_HI_OFF) + (uint32_t)row * ROWB + c8 * 16;
            }
            *reinterpret_cast<uint4*>(smem + soff) = v;
        }
        __syncthreads();

#pragma unroll
        for (int ks = 0; ks < 4; ks++) {
            int kk = ks * 16;

            uint32_t a_hi[2][4], a_lo[2][4];
#pragma unroll
            for (int mt = 0; mt < 2; mt++) {
                int m = wm * 32 + mt * 16 + (lane & 15);
                uint32_t byteoff = (uint32_t)m * ROWB +
                                   (uint32_t)(kk + (lane >> 4) * 8) * 2;
                LDSM_X4(a_hi[mt][0], a_hi[mt][1], a_hi[mt][2], a_hi[mt][3],
                        sb + A_HI_OFF + byteoff);
                LDSM_X4(a_lo[mt][0], a_lo[mt][1], a_lo[mt][2], a_lo[mt][3],
                        sb + A_LO_OFF + byteoff);
            }

#pragma unroll
            for (int ng = 0; ng < 4; ng++) {
                int g = lane >> 3;
                int n = wn * 64 + ng * 16 + (g >> 1) * 8 + (lane & 7);
                uint32_t byteoff = (uint32_t)n * ROWB +
                                   (uint32_t)(kk + (g & 1) * 8) * 2;
                uint32_t b_hi[4], b_lo[4];
                LDSM_X4(b_hi[0], b_hi[1], b_hi[2], b_hi[3], sb + B_HI_OFF + byteoff);
                LDSM_X4(b_lo[0], b_lo[1], b_lo[2], b_lo[3], sb + B_LO_OFF + byteoff);
#pragma unroll
                for (int mt = 0; mt < 2; mt++) {
#pragma unroll
                    for (int h = 0; h < 2; h++) {
                        int nt = ng * 2 + h;
                        MMA_BF16(acc[mt][nt], a_hi[mt], b_hi[h * 2], b_hi[h * 2 + 1]);
                        MMA_BF16(acc[mt][nt], a_hi[mt], b_lo[h * 2], b_lo[h * 2 + 1]);
                        MMA_BF16(acc[mt][nt], a_lo[mt], b_hi[h * 2], b_hi[h * 2 + 1]);
                    }
                }
            }
        }
        __syncthreads();
    }

#pragma unroll
    for (int mt = 0; mt < 2; mt++) {
        int r0 = blockRow + wm * 32 + mt * 16 + (lane >> 2);
        int r1 = r0 + 8;
#pragma unroll
        for (int nt = 0; nt < 8; nt++) {
            int cb = wn * 64 + nt * 8 + (lane & 3) * 2;
            float2 bb = *reinterpret_cast<const float2*>(bias + cb);
            float2 o0, o1;
            o0.x = acc[mt][nt][0] + bb.x;
            o0.y = acc[mt][nt][1] + bb.y;
            o1.x = acc[mt][nt][2] + bb.x;
            o1.y = acc[mt][nt][3] + bb.y;
            *reinterpret_cast<float2*>(out + (size_t)r0 * 128 + cb) = o0;
            *reinterpret_cast<float2*>(out + (size_t)r1 * 128 + cb) = o1;
        }
    }
}

// ---------------------------------------------------------------------------
extern "C" void kernel_launch(void* const* d_in, const int* in_sizes, int n_in,
                              void* d_out, int out_size) {
    const float* ndata = (const float*)d_in[0];
    const int*   src   = (const int*)d_in[1];
    const int*   dst   = (const int*)d_in[2];
    const float* W     = (const float*)d_in[3];
    const float* b     = (const float*)d_in[4];
    float* out = (float*)d_out;

    (void)in_sizes; (void)n_in; (void)out_size;

    cudaFuncSetAttribute(k_gemm_mma, cudaFuncAttributeMaxDynamicSharedMemorySize,
                         SMEM_GEMM);

    k_head<<<(N_NODES * DFEAT / 4 + 255) / 256, 256>>>(ndata, W, dst);
    k_scan<<<SCAN_BLOCKS, 1024>>>();
    k_fill<<<(N_EDGES / 8 + 255) / 256, 256>>>(src, dst);
    {
        long long threads = (long long)N_NODES * 32;
        int blocks = (int)((threads + 255) / 256);
        k_gather<<<blocks, 256>>>(ndata);
    }
    k_gemm_mma<<<250, 320, SMEM_GEMM>>>(b, out);
}